// round 7
// baseline (speedup 1.0000x reference)
#include <cuda_runtime.h>
#include <cuda_bf16.h>
#include <math.h>

// ---------------- problem constants ----------------
#define U_NN   50000
#define I_NN   25000
#define DD     64
#define DT     192
#define RR     2
#define LL     2
#define E_UI   500000
#define E_TR   600000
#define E_II   400000
#define BB     512
#define KK     100
#define EPSV   1e-8f
#define ROWB   (DT * 4)          // 768-byte stride of all feature tables

// CSR: user graph has 2 bins per user (r=0 segment then r=1 segment, contiguous).
//  bins [0,100000): user (2u+r)   [100000,125000): train   [125000,150000): ig0
//  [150000,175000): ig1
#define NTOT   175000
#define ETOT   2400000
#define DBU 0
#define DB2 100000
#define DB3 125000
#define DB4 150000
#define EB2 1000000
#define EB3 1600000
#define EB4 2000000

// ---------------- device scratch ----------------
__device__ __align__(16) float g_Uf[U_NN * DT];
__device__ __align__(16) float g_If[I_NN * DT];
__device__ __align__(16) float g_Sf[RR][I_NN * DT];
__device__ __align__(16) float g_Uagg[U_NN * DD];
__device__ __align__(16) float g_Iagg[I_NN * DD];
__device__ __align__(16) float g_IGagg[RR][I_NN * DD];
__device__            float g_cuser[U_NN * RR];
__device__            float g_invig[RR][I_NN];
__device__            float g_invdeg[I_NN];
__device__            int   g_cnt[NTOT];      // INVARIANT: zero at kernel_launch entry
__device__            int   g_off[NTOT];
__device__            int   g_cur[NTOT];
__device__ __align__(16) int g_srcA[ETOT];    // premultiplied byte offsets (src*768)
__device__ __align__(16) float g_G[RR][DT * DT];
__device__ __align__(16) float g_z[RR][BB * DT];

#define ADDX2(d, a, b) asm("add.rn.f32x2 %0, %1, %2;" : "=l"(d) : "l"(a), "l"(b))

// ---------------- launch 1: init (copies/coeffs) + histogram -------------
__global__ void k_init_hist(const float* __restrict__ ue, const float* __restrict__ ie,
                            const int* __restrict__ ubd, const int* __restrict__ igd,
                            const float* __restrict__ mgnn,
                            const int* __restrict__ rel_r, const int* __restrict__ tr_c,
                            const int* __restrict__ ig_r) {
    int t = blockIdx.x * blockDim.x + threadIdx.x;
    if (t < ETOT) {
        int d;
        if (t < EB2)       d = DBU + rel_r[t] * 2 + (t >= E_UI ? 1 : 0);
        else if (t < EB3)  d = DB2 + tr_c[t - EB2];
        else if (t < EB4)  d = DB3 + ig_r[t - EB3];
        else               d = DB4 + ig_r[E_II + (t - EB4)];
        atomicAdd(&g_cnt[d], 1);
    }
    if (t < U_NN) {
        float m0 = mgnn[0], m1 = mgnn[1];
        float mx = fmaxf(m0, m1);
        float e0 = expf(m0 - mx), e1 = expf(m1 - mx);
        float inv = 1.0f / (e0 + e1);
        float w0 = e0 * inv, w1 = e1 * inv;
        float d0 = (float)ubd[t * 2 + 0], d1 = (float)ubd[t * 2 + 1];
        float itot = 1.0f / (d0 * w0 + d1 * w1 + EPSV);
        g_cuser[t * 2 + 0] = d0 * w0 * itot / (d0 + EPSV);
        g_cuser[t * 2 + 1] = d1 * w1 * itot / (d1 + EPSV);
    }
    if (t < I_NN) {
        g_invig[0][t] = 1.0f / ((float)igd[0 * I_NN + t] + EPSV);
        g_invig[1][t] = 1.0f / ((float)igd[1 * I_NN + t] + EPSV);
    }
    int nU = U_NN * DD;
    if (t < nU) {
        int u = t >> 6, c = t & 63;
        g_Uf[u * DT + c] = ue[t];
    } else if (t < nU + I_NN * DD) {
        int j = t - nU;
        int i = j >> 6, c = j & 63;
        float v = ie[j];
        g_If[i * DT + c] = v;
        g_Sf[0][i * DT + c] = v;
        g_Sf[1][i * DT + c] = v;
    }
}

// ---------------- launch 2: scan (offsets + cursors + invdeg) -------------
__global__ void k_scan() {
    __shared__ int sh[1024];
    const int DBv[4] = {DBU, DB2, DB3, DB4};
    const int DSv[4] = {2 * U_NN, I_NN, I_NN, I_NN};
    int gsel = blockIdx.x;
    int base = DBv[gsel], size = DSv[gsel];
    int t = threadIdx.x;
    int chunk = (size + 1023) >> 10;
    int lo = t * chunk;
    int hi = lo + chunk; if (hi > size) hi = size;
    if (lo > size) lo = size;
    int s = 0;
    for (int i = lo; i < hi; i++) s += g_cnt[base + i];
    sh[t] = s;
    __syncthreads();
    for (int off = 1; off < 1024; off <<= 1) {
        int v = (t >= off) ? sh[t - off] : 0;
        __syncthreads();
        sh[t] += v;
        __syncthreads();
    }
    int run = (t > 0) ? sh[t - 1] : 0;
    for (int i = lo; i < hi; i++) {
        g_off[base + i] = run;
        g_cur[base + i] = run;
        run += g_cnt[base + i];
    }
    if (gsel == 1) {
        for (int i = lo; i < hi; i++)
            g_invdeg[i] = 1.0f / ((float)g_cnt[DB2 + i] + EPSV);
    }
}

// ---------------- launch 3: place (premultiplied byte offsets) ------------
__global__ void k_place_all(const int* __restrict__ rel_r, const int* __restrict__ rel_c,
                            const int* __restrict__ tr_r, const int* __restrict__ tr_c,
                            const int* __restrict__ ig_r, const int* __restrict__ ig_c) {
    int e = blockIdx.x * blockDim.x + threadIdx.x;
    if (e >= ETOT) return;
    int d, src, ebase;
    if (e < EB2) {
        d = DBU + rel_r[e] * 2 + (e >= E_UI ? 1 : 0);
        src = rel_c[e]; ebase = 0;
    } else if (e < EB3) {
        int j = e - EB2; d = DB2 + tr_c[j]; src = tr_r[j]; ebase = EB2;
    } else if (e < EB4) {
        int j = e - EB3; d = DB3 + ig_r[j]; src = ig_c[j]; ebase = EB3;
    } else {
        int j = e - EB4; d = DB4 + ig_r[E_II + j]; src = ig_c[E_II + j]; ebase = EB4;
    }
    int p = atomicAdd(&g_cur[d], 1);
    g_srcA[ebase + p] = src * ROWB;
}

// ---------------- core gather: packed f32x2 adds, int4 idx batches --------
// fb = (char*)(feature + colOff) + 8*lane ; list entries are byte offsets.
__device__ __forceinline__ float2 sum_f2(const int* __restrict__ base, int start, int deg,
                                         const char* __restrict__ fb) {
    unsigned long long a0 = 0ull, a1 = 0ull, a2 = 0ull, a3 = 0ull;
    int j = start, end = start + deg;
    // scalar prologue to 16B alignment of base+j
    while ((j & 3) && j < end) {
        int p = __ldg(base + j);
        unsigned long long v = *reinterpret_cast<const unsigned long long*>(fb + p);
        ADDX2(a0, a0, v);
        j++;
    }
    for (; j + 8 <= end; j += 8) {
        int4 q0 = *reinterpret_cast<const int4*>(base + j);
        int4 q1 = *reinterpret_cast<const int4*>(base + j + 4);
        unsigned long long v0 = *reinterpret_cast<const unsigned long long*>(fb + q0.x);
        unsigned long long v1 = *reinterpret_cast<const unsigned long long*>(fb + q0.y);
        unsigned long long v2 = *reinterpret_cast<const unsigned long long*>(fb + q0.z);
        unsigned long long v3 = *reinterpret_cast<const unsigned long long*>(fb + q0.w);
        unsigned long long v4 = *reinterpret_cast<const unsigned long long*>(fb + q1.x);
        unsigned long long v5 = *reinterpret_cast<const unsigned long long*>(fb + q1.y);
        unsigned long long v6 = *reinterpret_cast<const unsigned long long*>(fb + q1.z);
        unsigned long long v7 = *reinterpret_cast<const unsigned long long*>(fb + q1.w);
        ADDX2(a0, a0, v0); ADDX2(a1, a1, v1);
        ADDX2(a2, a2, v2); ADDX2(a3, a3, v3);
        ADDX2(a0, a0, v4); ADDX2(a1, a1, v5);
        ADDX2(a2, a2, v6); ADDX2(a3, a3, v7);
    }
    for (; j < end; j++) {
        int p = __ldg(base + j);
        unsigned long long v = *reinterpret_cast<const unsigned long long*>(fb + p);
        ADDX2(a0, a0, v);
    }
    ADDX2(a0, a0, a1);
    ADDX2(a2, a2, a3);
    ADDX2(a0, a0, a2);
    float2 r;
    r.x = __uint_as_float((unsigned)(a0 & 0xFFFFFFFFull));
    r.y = __uint_as_float((unsigned)(a0 >> 32));
    return r;
}

// ---------------- launch 4/6: fused gather (warp per destination) ---------
__global__ void __launch_bounds__(256, 6) k_gather_all(int colOff) {
    int w = (blockIdx.x * blockDim.x + threadIdx.x) >> 5;
    if (w >= U_NN + 3 * I_NN) return;
    int lane = threadIdx.x & 31;
    float2 r;
    float* dst;
    int row;
    if (w < U_NN) {
        const char* fb = (const char*)(g_If + colOff) + 8 * lane;
        int b0 = DBU + 2 * w;
        int s0 = g_off[b0],     d0 = g_cnt[b0];
        int s1 = g_off[b0 + 1], d1 = g_cnt[b0 + 1];
        float2 f0 = sum_f2(g_srcA, s0, d0, fb);
        float2 f1 = sum_f2(g_srcA, s1, d1, fb);
        float c0 = g_cuser[w * 2 + 0], c1 = g_cuser[w * 2 + 1];
        r.x = c0 * f0.x + c1 * f1.x;
        r.y = c0 * f0.y + c1 * f1.y;
        dst = g_Uagg; row = w;
    } else {
        int v = w - U_NN;
        int gsel = v / I_NN;
        int i = v - gsel * I_NN;
        float2 a; float c;
        if (gsel == 0) {
            a = sum_f2(g_srcA + EB2, g_off[DB2 + i], g_cnt[DB2 + i],
                       (const char*)(g_Uf + colOff) + 8 * lane);
            c = g_invdeg[i]; dst = g_Iagg;
        } else if (gsel == 1) {
            a = sum_f2(g_srcA + EB3, g_off[DB3 + i], g_cnt[DB3 + i],
                       (const char*)(g_If + colOff) + 8 * lane);
            c = g_invig[0][i]; dst = g_IGagg[0];
        } else {
            a = sum_f2(g_srcA + EB4, g_off[DB4 + i], g_cnt[DB4 + i],
                       (const char*)(g_If + colOff) + 8 * lane);
            c = g_invig[1][i]; dst = g_IGagg[1];
        }
        r = make_float2(a.x * c, a.y * c);
        row = i;
    }
    *reinterpret_cast<float2*>(&dst[(long)row * DD + lane * 2]) = r;
}

// ---------------- launch 5/7: fused dense projections ----------------
__global__ void k_gemm_all(const float* __restrict__ W_ui_l,
                           const float* __restrict__ W_ii0_l,
                           const float* __restrict__ W_ii1_l, int colOut) {
    __shared__ __align__(16) float Ws[64 * 64];
    __shared__ __align__(16) float As[64 * 68];
    int sel = blockIdx.y;
    const float* src; float* dst; const float* W; int N;
    if (sel == 0)      { src = g_Uagg;     dst = g_Uf;    W = W_ui_l;  N = U_NN; }
    else if (sel == 1) { src = g_Iagg;     dst = g_If;    W = W_ui_l;  N = I_NN; }
    else if (sel == 2) { src = g_IGagg[0]; dst = g_Sf[0]; W = W_ii0_l; N = I_NN; }
    else               { src = g_IGagg[1]; dst = g_Sf[1]; W = W_ii1_l; N = I_NN; }
    int row0 = blockIdx.x * 64;
    if (row0 >= N) return;
    int tid = threadIdx.x;

    for (int i = tid; i < 4096; i += 256) Ws[i] = W[i];
    for (int i = tid; i < 4096; i += 256) {
        int rr = i >> 6, k = i & 63;
        float v = (row0 + rr < N) ? src[(long)(row0 + rr) * DD + k] : 0.f;
        As[k * 68 + rr] = v;
    }
    __syncthreads();

    int cg = tid & 15, rg = tid >> 4;
    float acc[4][4];
#pragma unroll
    for (int i = 0; i < 4; i++)
#pragma unroll
        for (int j = 0; j < 4; j++) acc[i][j] = 0.f;

#pragma unroll 8
    for (int k = 0; k < 64; k++) {
        float4 a4 = *reinterpret_cast<const float4*>(&As[k * 68 + rg * 4]);
        float4 w4 = *reinterpret_cast<const float4*>(&Ws[k * 64 + cg * 4]);
        float a[4] = {a4.x, a4.y, a4.z, a4.w};
        float w[4] = {w4.x, w4.y, w4.z, w4.w};
#pragma unroll
        for (int i = 0; i < 4; i++)
#pragma unroll
            for (int j = 0; j < 4; j++) acc[i][j] += a[i] * w[j];
    }
#pragma unroll
    for (int i = 0; i < 4; i++) {
        int row = row0 + rg * 4 + i;
        if (row < N) {
            float4 o = make_float4(acc[i][0], acc[i][1], acc[i][2], acc[i][3]);
            *reinterpret_cast<float4*>(&dst[(long)row * DT + colOut + cg * 4]) = o;
        }
    }
}

// ---------------- scoring ----------------
__global__ void k_G(const float* __restrict__ bW, float* out, int lossIdx) {
    __shared__ float Asm[32 * 192];
    __shared__ float Bsm[32 * 192];
    if (blockIdx.x == 0 && blockIdx.y == 0 && blockIdx.z == 0 && threadIdx.x == 0)
        out[lossIdx] = 0.f;
    int r = blockIdx.z;
    const float* W = bW + (long)r * DT * DT;
    int i0 = blockIdx.x * 32, j0 = blockIdx.y * 32;
    for (int t = threadIdx.x; t < 32 * 192; t += 256) {
        Asm[t] = W[(long)(i0 + t / 192) * DT + (t % 192)];
        Bsm[t] = W[(long)(j0 + t / 192) * DT + (t % 192)];
    }
    __syncthreads();
    int tj = threadIdx.x & 15, ti = threadIdx.x >> 4;
    float acc[2][2] = {{0.f, 0.f}, {0.f, 0.f}};
    for (int k = 0; k < 192; k++) {
        float a0 = Asm[(ti * 2 + 0) * 192 + k];
        float a1 = Asm[(ti * 2 + 1) * 192 + k];
        float b0 = Bsm[(tj * 2 + 0) * 192 + k];
        float b1 = Bsm[(tj * 2 + 1) * 192 + k];
        acc[0][0] += a0 * b0; acc[0][1] += a0 * b1;
        acc[1][0] += a1 * b0; acc[1][1] += a1 * b1;
    }
#pragma unroll
    for (int i = 0; i < 2; i++)
#pragma unroll
        for (int j = 0; j < 2; j++)
            g_G[r][(long)(i0 + ti * 2 + i) * DT + (j0 + tj * 2 + j)] = acc[i][j];
}

// block per (b,r): aggregate batched user's rel-r segment, then z = agg @ G
__global__ void k_aggsel_z(const int* __restrict__ users, const int* __restrict__ ubd) {
    __shared__ float as[DT];
    int b = blockIdx.x, r = blockIdx.y, c = threadIdx.x;
    int u = users[b];
    int bin = DBU + 2 * u + r;
    int s = g_off[bin], deg = g_cnt[bin];
    const char* S = (const char*)g_Sf[r] + (long)c * 4;
    float a0 = 0.f, a1 = 0.f;
    int j = s, end = s + deg;
    for (; j + 2 <= end; j += 2) {
        int p0 = __ldg(&g_srcA[j]), p1 = __ldg(&g_srcA[j + 1]);
        a0 += *reinterpret_cast<const float*>(S + p0);
        a1 += *reinterpret_cast<const float*>(S + p1);
    }
    if (j < end) a0 += *reinterpret_cast<const float*>(S + __ldg(&g_srcA[j]));
    float coeff = 1.0f / ((float)ubd[u * 2 + r] + EPSV);
    as[c] = (a0 + a1) * coeff;
    __syncthreads();
    float acc = 0.f;
    const float* G = g_G[r];
#pragma unroll 4
    for (int k = 0; k < DT; k++) acc += as[k] * G[(long)k * DT + c];
    g_z[r][(long)b * DT + c] = acc;
}

// warp per (b,k); also restores the g_cnt==0 invariant for the next call
__global__ void k_score(const int* __restrict__ users, const int* __restrict__ items,
                        float* out, int lossIdx) {
    __shared__ float l2blk;
    int tg = blockIdx.x * blockDim.x + threadIdx.x;
    if (tg < NTOT) g_cnt[tg] = 0;
    if (threadIdx.x == 0) l2blk = 0.f;
    __syncthreads();
    int w = tg >> 5;
    int lane = threadIdx.x & 31;
    if (w < BB * KK) {
        int b = w / KK;
        int kk = w - b * KK;
        int u = users[b];
        int it = items[w];
        float s1 = 0.f, s2a = 0.f, s2b = 0.f, l2i = 0.f, l2u = 0.f;
        for (int c = lane; c < DT; c += 32) {
            float bu = g_Uf[(long)u * DT + c];
            float bi = g_If[(long)it * DT + c];
            s1 += bu * bi;
            l2i += bi * bi;
            if (kk == 0) l2u += bu * bu;
            s2a += g_z[0][(long)b * DT + c] * g_Sf[0][(long)it * DT + c];
            s2b += g_z[1][(long)b * DT + c] * g_Sf[1][(long)it * DT + c];
        }
#pragma unroll
        for (int off = 16; off; off >>= 1) {
            s1  += __shfl_down_sync(0xffffffffu, s1, off);
            s2a += __shfl_down_sync(0xffffffffu, s2a, off);
            s2b += __shfl_down_sync(0xffffffffu, s2b, off);
            l2i += __shfl_down_sync(0xffffffffu, l2i, off);
            if (kk == 0) l2u += __shfl_down_sync(0xffffffffu, l2u, off);
        }
        if (lane == 0) {
            out[w] = 0.5f * s1 + 0.25f * (s2a + s2b);
            atomicAdd(&l2blk, l2i + (kk == 0 ? (float)KK * l2u : 0.f));
        }
    }
    __syncthreads();
    if (threadIdx.x == 0) atomicAdd(out + lossIdx, 1e-4f * l2blk);
}

// ---------------- launch ----------------
extern "C" void kernel_launch(void* const* d_in, const int* in_sizes, int n_in,
                              void* d_out, int out_size) {
    const float* ue    = (const float*)d_in[0];
    const float* ie    = (const float*)d_in[1];
    const float* W_ui  = (const float*)d_in[2];
    const float* W_ii  = (const float*)d_in[3];
    const float* bW    = (const float*)d_in[4];
    const float* mgnn  = (const float*)d_in[5];
    const int* rel_r   = (const int*)d_in[6];
    const int* rel_c   = (const int*)d_in[7];
    const int* tr_r    = (const int*)d_in[8];
    const int* tr_c    = (const int*)d_in[9];
    const int* ig_r    = (const int*)d_in[10];
    const int* ig_c    = (const int*)d_in[11];
    const int* ubd     = (const int*)d_in[12];
    const int* igd     = (const int*)d_in[13];
    const int* users   = (const int*)d_in[14];
    const int* items   = (const int*)d_in[15];
    float* out = (float*)d_out;
    int lossIdx = out_size - 1;

    const int T = 256;
    auto g = [](long n, int t) { return (int)((n + t - 1) / t); };

    // 1-3: init + CSR build (g_cnt zero-at-entry invariant; k_score restores it)
    k_init_hist<<<g((long)(U_NN + I_NN) * DD, T), T>>>(ue, ie, ubd, igd, mgnn,
                                                       rel_r, tr_c, ig_r);
    k_scan<<<4, 1024>>>();
    k_place_all<<<g(ETOT, T), T>>>(rel_r, rel_c, tr_r, tr_c, ig_r, ig_c);

    // 4-7: two propagation layers
    for (int l = 0; l < LL; l++) {
        k_gather_all<<<g((long)(U_NN + 3 * I_NN) * 32, T), T>>>(l * DD);
        dim3 gg(g(U_NN, 64), 4);
        k_gemm_all<<<gg, 256>>>(W_ui + (long)l * DD * DD,
                                W_ii + (long)(0 * LL + l) * DD * DD,
                                W_ii + (long)(1 * LL + l) * DD * DD,
                                (l + 1) * DD);
    }

    // 8-10: scoring
    {
        dim3 ggG(6, 6, 2);
        k_G<<<ggG, 256>>>(bW, out, lossIdx);
    }
    {
        dim3 gz(BB, RR);
        k_aggsel_z<<<gz, DT>>>(users, ubd);
    }
    k_score<<<g((long)BB * KK * 32, T), T>>>(users, items, out, lossIdx);
}

// round 8
// speedup vs baseline: 1.2674x; 1.2674x over previous
#include <cuda_runtime.h>
#include <cuda_bf16.h>
#include <math.h>

// ---------------- problem constants ----------------
#define U_NN   50000
#define I_NN   25000
#define DD     64
#define DT     192
#define RR     2
#define LL     2
#define E_UI   500000
#define E_TR   600000
#define E_II   400000
#define BB     512
#define KK     100
#define EPSV   1e-8f

// CSR: 4 graphs (R6 layout).
//  gU: merged rel (dst=user, src=item packed with r in bit16), 1M edges
//  g2: train (dst=item, src=user)   g3/g4: ig r=0/1 (dst=item, src=item)
#define NTOT   125000
#define ETOT   2400000
#define DBU 0
#define DB2 50000
#define DB3 75000
#define DB4 100000
#define EB2 1000000
#define EB3 1600000
#define EB4 2000000
#define RBIT 0x10000

// ---------------- device scratch (dense [N,64] per-layer tables) ----------
__device__ __align__(16) float g_U1[U_NN * DD];
__device__ __align__(16) float g_U2[U_NN * DD];
__device__ __align__(16) float g_I1[I_NN * DD];
__device__ __align__(16) float g_I2[I_NN * DD];
__device__ __align__(16) float g_S1[RR][I_NN * DD];
__device__ __align__(16) float g_S2[RR][I_NN * DD];
__device__ __align__(16) float g_Uagg[U_NN * DD];
__device__ __align__(16) float g_Iagg[I_NN * DD];
__device__ __align__(16) float g_IGagg[RR][I_NN * DD];
__device__            float g_cuser[U_NN * RR];
__device__            float g_invig[RR][I_NN];
__device__            float g_invdeg[I_NN];
__device__            int   g_cnt[NTOT];      // INVARIANT: zero at kernel_launch entry
__device__            int   g_off[NTOT];
__device__            int   g_cur[NTOT];
__device__            int   g_srcA[ETOT];
__device__ __align__(16) float g_G[RR][DT * DT];
__device__ __align__(16) float g_z[RR][BB * DT];

// ---------------- launch 1: coeffs + histogram (no copies) ----------------
__global__ void k_init_hist(const int* __restrict__ ubd, const int* __restrict__ igd,
                            const float* __restrict__ mgnn,
                            const int* __restrict__ rel_r, const int* __restrict__ tr_c,
                            const int* __restrict__ ig_r) {
    int t = blockIdx.x * blockDim.x + threadIdx.x;
    if (t < ETOT) {
        int d;
        if (t < EB2)       d = DBU + rel_r[t];
        else if (t < EB3)  d = DB2 + tr_c[t - EB2];
        else if (t < EB4)  d = DB3 + ig_r[t - EB3];
        else               d = DB4 + ig_r[E_II + (t - EB4)];
        atomicAdd(&g_cnt[d], 1);
    }
    if (t < U_NN) {
        float m0 = mgnn[0], m1 = mgnn[1];
        float mx = fmaxf(m0, m1);
        float e0 = expf(m0 - mx), e1 = expf(m1 - mx);
        float inv = 1.0f / (e0 + e1);
        float w0 = e0 * inv, w1 = e1 * inv;
        float d0 = (float)ubd[t * 2 + 0], d1 = (float)ubd[t * 2 + 1];
        float itot = 1.0f / (d0 * w0 + d1 * w1 + EPSV);
        g_cuser[t * 2 + 0] = d0 * w0 * itot / (d0 + EPSV);
        g_cuser[t * 2 + 1] = d1 * w1 * itot / (d1 + EPSV);
    }
    if (t < I_NN) {
        g_invig[0][t] = 1.0f / ((float)igd[0 * I_NN + t] + EPSV);
        g_invig[1][t] = 1.0f / ((float)igd[1 * I_NN + t] + EPSV);
    }
}

// ---------------- launch 2: scan (offsets + cursors + invdeg) -------------
__global__ void k_scan() {
    __shared__ int sh[1024];
    const int DBv[4] = {DBU, DB2, DB3, DB4};
    const int DSv[4] = {U_NN, I_NN, I_NN, I_NN};
    int gsel = blockIdx.x;
    int base = DBv[gsel], size = DSv[gsel];
    int t = threadIdx.x;
    int chunk = (size + 1023) >> 10;
    int lo = t * chunk;
    int hi = lo + chunk; if (hi > size) hi = size;
    if (lo > size) lo = size;
    int s = 0;
    for (int i = lo; i < hi; i++) s += g_cnt[base + i];
    sh[t] = s;
    __syncthreads();
    for (int off = 1; off < 1024; off <<= 1) {
        int v = (t >= off) ? sh[t - off] : 0;
        __syncthreads();
        sh[t] += v;
        __syncthreads();
    }
    int run = (t > 0) ? sh[t - 1] : 0;
    for (int i = lo; i < hi; i++) {
        g_off[base + i] = run;
        g_cur[base + i] = run;
        run += g_cnt[base + i];
    }
    if (gsel == 1) {
        for (int i = lo; i < hi; i++)
            g_invdeg[i] = 1.0f / ((float)g_cnt[DB2 + i] + EPSV);
    }
}

// ---------------- launch 3: place ----------------
__global__ void k_place_all(const int* __restrict__ rel_r, const int* __restrict__ rel_c,
                            const int* __restrict__ tr_r, const int* __restrict__ tr_c,
                            const int* __restrict__ ig_r, const int* __restrict__ ig_c) {
    int e = blockIdx.x * blockDim.x + threadIdx.x;
    if (e >= ETOT) return;
    int d, src, ebase;
    if (e < EB2) {
        d = DBU + rel_r[e];
        src = rel_c[e] + ((e >= E_UI) ? RBIT : 0);
        ebase = 0;
    } else if (e < EB3) {
        int j = e - EB2; d = DB2 + tr_c[j]; src = tr_r[j]; ebase = EB2;
    } else if (e < EB4) {
        int j = e - EB3; d = DB3 + ig_r[j]; src = ig_c[j]; ebase = EB3;
    } else {
        int j = e - EB4; d = DB4 + ig_r[E_II + j]; src = ig_c[E_II + j]; ebase = EB4;
    }
    int p = atomicAdd(&g_cur[d], 1);
    g_srcA[ebase + p] = src;
}

// ---------------- gather: lane owns 2 columns, broadcast idx loads --------
// fb = dense table + 2*lane ; rows are DD floats.
template <bool WEIGHTED>
__device__ __forceinline__ float2 gather_f2(const int* __restrict__ lst, int deg,
                                            const float* __restrict__ fb,
                                            float c0, float c1) {
    float ax0 = 0.f, ay0 = 0.f, ax1 = 0.f, ay1 = 0.f;
    float ax2 = 0.f, ay2 = 0.f, ax3 = 0.f, ay3 = 0.f;
    int j = 0;
    for (; j + 8 <= deg; j += 8) {
        int p0 = __ldg(lst + j + 0), p1 = __ldg(lst + j + 1);
        int p2 = __ldg(lst + j + 2), p3 = __ldg(lst + j + 3);
        int p4 = __ldg(lst + j + 4), p5 = __ldg(lst + j + 5);
        int p6 = __ldg(lst + j + 6), p7 = __ldg(lst + j + 7);
        float w0 = 1.f, w1 = 1.f, w2 = 1.f, w3 = 1.f;
        float w4 = 1.f, w5 = 1.f, w6 = 1.f, w7 = 1.f;
        if (WEIGHTED) {
            w0 = (p0 & RBIT) ? c1 : c0; p0 &= 0xFFFF;
            w1 = (p1 & RBIT) ? c1 : c0; p1 &= 0xFFFF;
            w2 = (p2 & RBIT) ? c1 : c0; p2 &= 0xFFFF;
            w3 = (p3 & RBIT) ? c1 : c0; p3 &= 0xFFFF;
            w4 = (p4 & RBIT) ? c1 : c0; p4 &= 0xFFFF;
            w5 = (p5 & RBIT) ? c1 : c0; p5 &= 0xFFFF;
            w6 = (p6 & RBIT) ? c1 : c0; p6 &= 0xFFFF;
            w7 = (p7 & RBIT) ? c1 : c0; p7 &= 0xFFFF;
        }
        float2 v0 = *reinterpret_cast<const float2*>(fb + (long)p0 * DD);
        float2 v1 = *reinterpret_cast<const float2*>(fb + (long)p1 * DD);
        float2 v2 = *reinterpret_cast<const float2*>(fb + (long)p2 * DD);
        float2 v3 = *reinterpret_cast<const float2*>(fb + (long)p3 * DD);
        float2 v4 = *reinterpret_cast<const float2*>(fb + (long)p4 * DD);
        float2 v5 = *reinterpret_cast<const float2*>(fb + (long)p5 * DD);
        float2 v6 = *reinterpret_cast<const float2*>(fb + (long)p6 * DD);
        float2 v7 = *reinterpret_cast<const float2*>(fb + (long)p7 * DD);
        ax0 += w0 * v0.x; ay0 += w0 * v0.y;
        ax1 += w1 * v1.x; ay1 += w1 * v1.y;
        ax2 += w2 * v2.x; ay2 += w2 * v2.y;
        ax3 += w3 * v3.x; ay3 += w3 * v3.y;
        ax0 += w4 * v4.x; ay0 += w4 * v4.y;
        ax1 += w5 * v5.x; ay1 += w5 * v5.y;
        ax2 += w6 * v6.x; ay2 += w6 * v6.y;
        ax3 += w7 * v7.x; ay3 += w7 * v7.y;
    }
    for (; j < deg; j++) {
        int p = __ldg(lst + j);
        float w = 1.f;
        if (WEIGHTED) { w = (p & RBIT) ? c1 : c0; p &= 0xFFFF; }
        float2 v = *reinterpret_cast<const float2*>(fb + (long)p * DD);
        ax0 += w * v.x; ay0 += w * v.y;
    }
    return make_float2(ax0 + ax1 + ax2 + ax3, ay0 + ay1 + ay2 + ay3);
}

// ---------------- launch 4/6: fused gather (warp per destination) ---------
// uSrc = user-path table at this layer, iSrc = item-path table at this layer.
__global__ void __launch_bounds__(256, 6) k_gather_all(const float* __restrict__ uSrc,
                                                       const float* __restrict__ iSrc) {
    int w = (blockIdx.x * blockDim.x + threadIdx.x) >> 5;
    if (w >= U_NN + 3 * I_NN) return;
    int lane = threadIdx.x & 31;
    int c2 = lane * 2;
    float2 r;
    float* dst;
    int row;
    if (w < U_NN) {
        int u = w;
        float c0 = g_cuser[u * 2 + 0], c1 = g_cuser[u * 2 + 1];
        r = gather_f2<true>(g_srcA + g_off[DBU + u], g_cnt[DBU + u],
                            iSrc + c2, c0, c1);
        dst = g_Uagg; row = u;
    } else {
        int v = w - U_NN;
        int gsel = v / I_NN;
        int i = v - gsel * I_NN;
        float2 a; float c;
        if (gsel == 0) {
            a = gather_f2<false>(g_srcA + EB2 + g_off[DB2 + i], g_cnt[DB2 + i],
                                 uSrc + c2, 0.f, 0.f);
            c = g_invdeg[i]; dst = g_Iagg;
        } else if (gsel == 1) {
            a = gather_f2<false>(g_srcA + EB3 + g_off[DB3 + i], g_cnt[DB3 + i],
                                 iSrc + c2, 0.f, 0.f);
            c = g_invig[0][i]; dst = g_IGagg[0];
        } else {
            a = gather_f2<false>(g_srcA + EB4 + g_off[DB4 + i], g_cnt[DB4 + i],
                                 iSrc + c2, 0.f, 0.f);
            c = g_invig[1][i]; dst = g_IGagg[1];
        }
        r = make_float2(a.x * c, a.y * c);
        row = i;
    }
    *reinterpret_cast<float2*>(&dst[(long)row * DD + c2]) = r;
}

// ---------------- launch 5/7: fused dense projections (dense outputs) -----
__global__ void k_gemm_all(const float* __restrict__ W_ui_l,
                           const float* __restrict__ W_ii0_l,
                           const float* __restrict__ W_ii1_l,
                           float* __restrict__ Udst, float* __restrict__ Idst,
                           float* __restrict__ S0dst, float* __restrict__ S1dst) {
    __shared__ __align__(16) float Ws[64 * 64];
    __shared__ __align__(16) float As[64 * 68];
    int sel = blockIdx.y;
    const float* src; float* dst; const float* W; int N;
    if (sel == 0)      { src = g_Uagg;     dst = Udst;  W = W_ui_l;  N = U_NN; }
    else if (sel == 1) { src = g_Iagg;     dst = Idst;  W = W_ui_l;  N = I_NN; }
    else if (sel == 2) { src = g_IGagg[0]; dst = S0dst; W = W_ii0_l; N = I_NN; }
    else               { src = g_IGagg[1]; dst = S1dst; W = W_ii1_l; N = I_NN; }
    int row0 = blockIdx.x * 64;
    if (row0 >= N) return;
    int tid = threadIdx.x;

    for (int i = tid; i < 4096; i += 256) Ws[i] = W[i];
    for (int i = tid; i < 4096; i += 256) {
        int rr = i >> 6, k = i & 63;
        float v = (row0 + rr < N) ? src[(long)(row0 + rr) * DD + k] : 0.f;
        As[k * 68 + rr] = v;
    }
    __syncthreads();

    int cg = tid & 15, rg = tid >> 4;
    float acc[4][4];
#pragma unroll
    for (int i = 0; i < 4; i++)
#pragma unroll
        for (int j = 0; j < 4; j++) acc[i][j] = 0.f;

#pragma unroll 8
    for (int k = 0; k < 64; k++) {
        float4 a4 = *reinterpret_cast<const float4*>(&As[k * 68 + rg * 4]);
        float4 w4 = *reinterpret_cast<const float4*>(&Ws[k * 64 + cg * 4]);
        float a[4] = {a4.x, a4.y, a4.z, a4.w};
        float w[4] = {w4.x, w4.y, w4.z, w4.w};
#pragma unroll
        for (int i = 0; i < 4; i++)
#pragma unroll
            for (int j = 0; j < 4; j++) acc[i][j] += a[i] * w[j];
    }
#pragma unroll
    for (int i = 0; i < 4; i++) {
        int row = row0 + rg * 4 + i;
        if (row < N) {
            float4 o = make_float4(acc[i][0], acc[i][1], acc[i][2], acc[i][3]);
            *reinterpret_cast<float4*>(&dst[(long)row * DD + cg * 4]) = o;
        }
    }
}

// ---------------- scoring ----------------
__global__ void k_G(const float* __restrict__ bW, float* out, int lossIdx) {
    __shared__ float Asm[32 * 192];
    __shared__ float Bsm[32 * 192];
    if (blockIdx.x == 0 && blockIdx.y == 0 && blockIdx.z == 0 && threadIdx.x == 0)
        out[lossIdx] = 0.f;
    int r = blockIdx.z;
    const float* W = bW + (long)r * DT * DT;
    int i0 = blockIdx.x * 32, j0 = blockIdx.y * 32;
    for (int t = threadIdx.x; t < 32 * 192; t += 256) {
        Asm[t] = W[(long)(i0 + t / 192) * DT + (t % 192)];
        Bsm[t] = W[(long)(j0 + t / 192) * DT + (t % 192)];
    }
    __syncthreads();
    int tj = threadIdx.x & 15, ti = threadIdx.x >> 4;
    float acc[2][2] = {{0.f, 0.f}, {0.f, 0.f}};
    for (int k = 0; k < 192; k++) {
        float a0 = Asm[(ti * 2 + 0) * 192 + k];
        float a1 = Asm[(ti * 2 + 1) * 192 + k];
        float b0 = Bsm[(tj * 2 + 0) * 192 + k];
        float b1 = Bsm[(tj * 2 + 1) * 192 + k];
        acc[0][0] += a0 * b0; acc[0][1] += a0 * b1;
        acc[1][0] += a1 * b0; acc[1][1] += a1 * b1;
    }
#pragma unroll
    for (int i = 0; i < 2; i++)
#pragma unroll
        for (int j = 0; j < 2; j++)
            g_G[r][(long)(i0 + ti * 2 + i) * DT + (j0 + tj * 2 + j)] = acc[i][j];
}

// block per (b,r): aggregate batched user's rel-r subset, then z = agg @ G
__global__ void k_aggsel_z(const int* __restrict__ users, const int* __restrict__ ubd,
                           const float* __restrict__ ie) {
    __shared__ float as[DT];
    int b = blockIdx.x, r = blockIdx.y, c = threadIdx.x;
    int u = users[b];
    const int* lst = g_srcA + g_off[DBU + u];
    int deg = g_cnt[DBU + u];
    int want = r ? RBIT : 0;
    // thread's column lives in one fixed segment table
    const float* T = (c < 64) ? ie : (c < 128) ? g_S1[r] : g_S2[r];
    int col = c & 63;
    float a0 = 0.f;
    for (int j = 0; j < deg; j++) {
        int p = __ldg(&lst[j]);
        if ((p & RBIT) == want)
            a0 += T[(long)(p & 0xFFFF) * DD + col];
    }
    float coeff = 1.0f / ((float)ubd[u * 2 + r] + EPSV);
    as[c] = a0 * coeff;
    __syncthreads();
    float acc = 0.f;
    const float* G = g_G[r];
#pragma unroll 4
    for (int k = 0; k < DT; k++) acc += as[k] * G[(long)k * DT + c];
    g_z[r][(long)b * DT + c] = acc;
}

// warp per (b,k); restores g_cnt==0 invariant
__global__ void k_score(const int* __restrict__ users, const int* __restrict__ items,
                        const float* __restrict__ ue, const float* __restrict__ ie,
                        float* out, int lossIdx) {
    __shared__ float l2blk;
    int tg = blockIdx.x * blockDim.x + threadIdx.x;
    if (tg < NTOT) g_cnt[tg] = 0;
    if (threadIdx.x == 0) l2blk = 0.f;
    __syncthreads();
    int w = tg >> 5;
    int lane = threadIdx.x & 31;
    if (w < BB * KK) {
        int b = w / KK;
        int kk = w - b * KK;
        int u = users[b];
        int it = items[w];
        float s1 = 0.f, s2a = 0.f, s2b = 0.f, l2i = 0.f, l2u = 0.f;
        const float* z0 = g_z[0] + (long)b * DT;
        const float* z1 = g_z[1] + (long)b * DT;
#pragma unroll
        for (int s = 0; s < 2; s++) {
            int c = lane + 32 * s;
            // segment 0: tables ue/ie (Sf seg0 == ie, reuse load)
            {
                float bu = ue[(long)u * DD + c];
                float bi = ie[(long)it * DD + c];
                s1 += bu * bi; l2i += bi * bi;
                if (kk == 0) l2u += bu * bu;
                s2a += z0[c] * bi;
                s2b += z1[c] * bi;
            }
            // segment 1
            {
                float bu = g_U1[(long)u * DD + c];
                float bi = g_I1[(long)it * DD + c];
                s1 += bu * bi; l2i += bi * bi;
                if (kk == 0) l2u += bu * bu;
                s2a += z0[64 + c] * g_S1[0][(long)it * DD + c];
                s2b += z1[64 + c] * g_S1[1][(long)it * DD + c];
            }
            // segment 2
            {
                float bu = g_U2[(long)u * DD + c];
                float bi = g_I2[(long)it * DD + c];
                s1 += bu * bi; l2i += bi * bi;
                if (kk == 0) l2u += bu * bu;
                s2a += z0[128 + c] * g_S2[0][(long)it * DD + c];
                s2b += z1[128 + c] * g_S2[1][(long)it * DD + c];
            }
        }
#pragma unroll
        for (int off = 16; off; off >>= 1) {
            s1  += __shfl_down_sync(0xffffffffu, s1, off);
            s2a += __shfl_down_sync(0xffffffffu, s2a, off);
            s2b += __shfl_down_sync(0xffffffffu, s2b, off);
            l2i += __shfl_down_sync(0xffffffffu, l2i, off);
            if (kk == 0) l2u += __shfl_down_sync(0xffffffffu, l2u, off);
        }
        if (lane == 0) {
            out[w] = 0.5f * s1 + 0.25f * (s2a + s2b);
            atomicAdd(&l2blk, l2i + (kk == 0 ? (float)KK * l2u : 0.f));
        }
    }
    __syncthreads();
    if (threadIdx.x == 0) atomicAdd(out + lossIdx, 1e-4f * l2blk);
}

// ---------------- launch ----------------
extern "C" void kernel_launch(void* const* d_in, const int* in_sizes, int n_in,
                              void* d_out, int out_size) {
    const float* ue    = (const float*)d_in[0];
    const float* ie    = (const float*)d_in[1];
    const float* W_ui  = (const float*)d_in[2];
    const float* W_ii  = (const float*)d_in[3];
    const float* bW    = (const float*)d_in[4];
    const float* mgnn  = (const float*)d_in[5];
    const int* rel_r   = (const int*)d_in[6];
    const int* rel_c   = (const int*)d_in[7];
    const int* tr_r    = (const int*)d_in[8];
    const int* tr_c    = (const int*)d_in[9];
    const int* ig_r    = (const int*)d_in[10];
    const int* ig_c    = (const int*)d_in[11];
    const int* ubd     = (const int*)d_in[12];
    const int* igd     = (const int*)d_in[13];
    const int* users   = (const int*)d_in[14];
    const int* items   = (const int*)d_in[15];
    float* out = (float*)d_out;
    int lossIdx = out_size - 1;

    const int T = 256;
    auto g = [](long n, int t) { return (int)((n + t - 1) / t); };

    // device-global table pointers for layer plumbing
    float *U1, *U2, *I1, *I2, *S10, *S11, *S20, *S21;
    cudaGetSymbolAddress((void**)&U1,  g_U1);
    cudaGetSymbolAddress((void**)&U2,  g_U2);
    cudaGetSymbolAddress((void**)&I1,  g_I1);
    cudaGetSymbolAddress((void**)&I2,  g_I2);
    cudaGetSymbolAddress((void**)&S10, g_S1);
    cudaGetSymbolAddress((void**)&S20, g_S2);
    S11 = S10 + I_NN * DD;
    S21 = S20 + I_NN * DD;

    // 1-3: init + CSR build (g_cnt zero-at-entry invariant; k_score restores it)
    k_init_hist<<<g(ETOT, T), T>>>(ubd, igd, mgnn, rel_r, tr_c, ig_r);
    k_scan<<<4, 1024>>>();
    k_place_all<<<g(ETOT, T), T>>>(rel_r, rel_c, tr_r, tr_c, ig_r, ig_c);

    // 4-7: two propagation layers (layer-0 tables ARE the inputs)
    {
        dim3 gg(g(U_NN, 64), 4);
        k_gather_all<<<g((long)(U_NN + 3 * I_NN) * 32, T), T>>>(ue, ie);
        k_gemm_all<<<gg, 256>>>(W_ui, W_ii, W_ii + (long)LL * DD * DD,
                                U1, I1, S10, S11);
        k_gather_all<<<g((long)(U_NN + 3 * I_NN) * 32, T), T>>>(U1, I1);
        k_gemm_all<<<gg, 256>>>(W_ui + (long)DD * DD,
                                W_ii + (long)DD * DD,
                                W_ii + (long)(LL + 1) * DD * DD,
                                U2, I2, S20, S21);
    }

    // 8-10: scoring
    {
        dim3 ggG(6, 6, 2);
        k_G<<<ggG, 256>>>(bW, out, lossIdx);
    }
    {
        dim3 gz(BB, RR);
        k_aggsel_z<<<gz, DT>>>(users, ubd, ie);
    }
    k_score<<<g((long)BB * KK * 32, T), T>>>(users, items, ue, ie, out, lossIdx);
}